// round 2
// baseline (speedup 1.0000x reference)
#include <cuda_runtime.h>
#include <cuda_bf16.h>
#include <math.h>

// Problem constants (fixed by the reference)
#define B       32
#define D       1024
#define VOCAB   50257
#define SEQ     128

// GEMM2 tiling
#define VLANES  128        // v-lanes per block
#define VT      3          // v columns per thread
#define VBLK    (VLANES*VT)   // 384 v per block
#define NBLK    ((VOCAB + VBLK - 1) / VBLK)   // 131
#define LSS     385        // logits smem stride (padded)

// GEMM1 k-split
#define KSPLIT  8

typedef unsigned long long ull;

// ---------------- device scratch (no allocations allowed) ----------------
__device__ float g_hT[D * B];                  // h transposed: [k][b], 128KB
__device__ float g_part[KSPLIT * B * D];       // GEMM1 partials, 1MB
__device__ float g_pmax[NBLK * B];
__device__ float g_psum[NBLK * B];
__device__ float g_pg[NBLK];
__device__ int   g_lab64;                      // 1 if labels are int64

__device__ __forceinline__ void ffma2(ull &acc, ull a, ull b) {
    asm("fma.rn.f32x2 %0, %1, %2, %0;" : "+l"(acc) : "l"(a), "l"(b));
}
__device__ __forceinline__ ull pack2(float w) {
    ull r; asm("mov.b64 %0, {%1, %1};" : "=l"(r) : "f"(w)); return r;
}
__device__ __forceinline__ void unpack2(ull v, float &lo, float &hi) {
    asm("mov.b64 {%0, %1}, %2;" : "=f"(lo), "=f"(hi) : "l"(v));
}

// ============== label dtype probe: int64 vs int32 (JAX x64-off) ===========
// Reads the first 2048 8-byte words — within the buffer for either dtype
// (int32: 4096*4B = 16KB; int64: 4096*8B = 32KB). If labels are int32,
// each word fuses two labels -> high word nonzero -> out of [0, VOCAB).
__global__ void detect_labels(const long long* __restrict__ labels)
{
    __shared__ int bad;
    if (threadIdx.x == 0) bad = 0;
    __syncthreads();
    for (int i = threadIdx.x; i < 2048; i += 256) {
        long long v = labels[i];
        if (v < 0 || v >= (long long)VOCAB) bad = 1;
    }
    __syncthreads();
    if (threadIdx.x == 0) g_lab64 = bad ? 0 : 1;
}

// ================= GEMM1 stage 1: partial z@W0 over a k-slice =============
// grid: 256 blocks = 32 j-tiles (32 cols) x 8 k-slices (128 k each), 256 thr
__global__ __launch_bounds__(256, 2) void g1_stage1(
    const float* __restrict__ z, const float* __restrict__ W0)
{
    __shared__ __align__(16) float zs[128 * 34];   // zT slice [kk][b], padded
    const int jt = blockIdx.x & 31;
    const int ks = blockIdx.x >> 5;
    const int j0 = jt * 32;
    const int k0 = ks * 128;
    const int t  = threadIdx.x;

    for (int i = t; i < B * 128; i += 256) {
        int bb = i >> 7, kk = i & 127;
        zs[kk * 34 + bb] = z[bb * D + k0 + kk];
    }
    __syncthreads();

    const int lane = t & 31;           // j within tile
    const int grp  = t >> 5;           // 8 groups of 4 b
    const int j    = j0 + lane;
    const int b0   = grp * 4;

    ull a0 = 0ull, a1 = 0ull;
    const ull* zs64 = (const ull*)zs;
    const float* pw = W0 + (size_t)k0 * D + j;

    #pragma unroll 8
    for (int kk = 0; kk < 128; ++kk) {
        float w = pw[kk * D];
        ull w2 = pack2(w);
        ull h0 = zs64[kk * 17 + (b0 >> 1)];
        ull h1 = zs64[kk * 17 + (b0 >> 1) + 1];
        ffma2(a0, h0, w2);
        ffma2(a1, h1, w2);
    }
    float f0, f1, f2, f3;
    unpack2(a0, f0, f1);
    unpack2(a1, f2, f3);
    float* dst = g_part + (size_t)ks * (B * D) + b0 * D + j;
    dst[0]      = f0;
    dst[D]      = f1;
    dst[2 * D]  = f2;
    dst[3 * D]  = f3;
}

// ============ GEMM1 stage 2: reduce k-splits, +bias, exact GELU ===========
// grid: 128 x 256
__global__ void g1_stage2(const float* __restrict__ b0v)
{
    int idx = blockIdx.x * 256 + threadIdx.x;   // 0..32767
    int bb = idx >> 10;
    int j  = idx & 1023;
    float s = b0v[j];
    #pragma unroll
    for (int ks = 0; ks < KSPLIT; ++ks)
        s += g_part[(size_t)ks * (B * D) + bb * D + j];
    float gel = 0.5f * s * (1.0f + erff(s * 0.70710678118654752f));
    g_hT[j * B + bb] = gel;     // transposed for GEMM2 smem broadcast pairs
}

// ======= GEMM2 + bias + partial logsumexp + label gather (the big one) ====
// grid: NBLK=131 blocks, 256 threads, 128KB dynamic smem for hT
__global__ __launch_bounds__(256, 1) void big_kernel(
    const float* __restrict__ W1, const float* __restrict__ b1,
    const void* __restrict__ labels)
{
    extern __shared__ __align__(16) float hs[];    // [k][b] = 32768 floats
    const int t = threadIdx.x;

    for (int i = t; i < D * B; i += 256) hs[i] = g_hT[i];
    __syncthreads();

    const int vl   = t & 127;
    const int grp  = t >> 7;           // 2 groups of 16 b
    const int b0   = grp * 16;
    const int vbase = blockIdx.x * VBLK;

    int  v[VT]; int vc[VT]; bool val[VT];
    #pragma unroll
    for (int j = 0; j < VT; ++j) {
        v[j]   = vbase + vl + 128 * j;
        val[j] = (v[j] < VOCAB);
        vc[j]  = val[j] ? v[j] : 0;
    }

    ull acc[8][VT];
    #pragma unroll
    for (int p = 0; p < 8; ++p)
        #pragma unroll
        for (int j = 0; j < VT; ++j) acc[p][j] = 0ull;

    const ull* hs64 = (const ull*)hs;
    const int hbase = b0 >> 1;          // pair index base (8*grp)
    const float* pw = W1;

    #pragma unroll 8
    for (int k = 0; k < D; ++k) {
        float w0 = pw[vc[0]];
        float w1v = pw[vc[1]];
        float w2v = pw[vc[2]];
        ull W[VT];
        W[0] = pack2(w0); W[1] = pack2(w1v); W[2] = pack2(w2v);
        ull hp[8];
        #pragma unroll
        for (int p = 0; p < 8; ++p) hp[p] = hs64[k * 16 + hbase + p];
        #pragma unroll
        for (int p = 0; p < 8; ++p) {
            ffma2(acc[p][0], hp[p], W[0]);
            ffma2(acc[p][1], hp[p], W[1]);
            ffma2(acc[p][2], hp[p], W[2]);
        }
        pw += VOCAB;
    }
    __syncthreads();                    // done reading hs; reuse as logits

    float* Ls = hs;                     // [b][LSS], 32*385*4 = 49.3KB < 128KB
    #pragma unroll
    for (int j = 0; j < VT; ++j) {
        const int vloc = vl + 128 * j;
        const float bias = val[j] ? b1[v[j]] : 0.f;
        #pragma unroll
        for (int p = 0; p < 8; ++p) {
            float lo, hi;
            unpack2(acc[p][j], lo, hi);
            float f0 = val[j] ? (lo + bias) : -1e30f;
            float f1 = val[j] ? (hi + bias) : -1e30f;
            Ls[(b0 + 2 * p)     * LSS + vloc] = f0;
            Ls[(b0 + 2 * p + 1) * LSS + vloc] = f1;
        }
    }
    __syncthreads();

    // label gather: sum of logits at labels that fall into this v-tile.
    // dtype of labels resolved at runtime by detect_labels (int64 vs int32).
    const int lab64 = g_lab64;
    const long long* lab_ll = (const long long*)labels;
    const int*       lab_i  = (const int*)labels;
    float g = 0.f;
    for (int i = t; i < B * SEQ; i += 256) {
        int bb = i >> 7;
        int lab = lab64 ? (int)lab_ll[i] : lab_i[i];
        int rel = lab - vbase;
        if (rel >= 0 && rel < VBLK) g += Ls[bb * LSS + rel];
    }
    __shared__ float red[256];
    red[t] = g;
    __syncthreads();
    for (int off = 128; off; off >>= 1) {
        if (t < off) red[t] += red[t + off];
        __syncthreads();
    }
    if (t == 0) g_pg[blockIdx.x] = red[0];

    // per-b partial (max, sumexp) over this block's 384 columns
    const int wid = t >> 5, lane = t & 31;
    #pragma unroll
    for (int bi = 0; bi < 4; ++bi) {
        const int bb = wid * 4 + bi;
        float m = -1e30f;
        for (int vv = lane; vv < VBLK; vv += 32)
            m = fmaxf(m, Ls[bb * LSS + vv]);
        #pragma unroll
        for (int o = 16; o; o >>= 1)
            m = fmaxf(m, __shfl_xor_sync(0xffffffffu, m, o));
        float s = 0.f;
        for (int vv = lane; vv < VBLK; vv += 32)
            s += __expf(Ls[bb * LSS + vv] - m);
        #pragma unroll
        for (int o = 16; o; o >>= 1)
            s += __shfl_xor_sync(0xffffffffu, s, o);
        if (lane == 0) {
            g_pmax[blockIdx.x * B + bb] = m;
            g_psum[blockIdx.x * B + bb] = s;
        }
    }
}

// ================= finalize: combine partials into the scalar =============
__global__ void finalize(float* __restrict__ out)
{
    __shared__ float smax[B][8];
    __shared__ float ssum[B][8];
    __shared__ float gmaxs[B];
    __shared__ float lses[B];
    __shared__ float red[256];
    const int t = threadIdx.x;
    const int b = t >> 3, p = t & 7;

    float m = -1e30f;
    for (int i = p; i < NBLK; i += 8) m = fmaxf(m, g_pmax[i * B + b]);
    smax[b][p] = m;
    __syncthreads();
    if (t < B) {
        float mm = -1e30f;
        #pragma unroll
        for (int q = 0; q < 8; ++q) mm = fmaxf(mm, smax[t][q]);
        gmaxs[t] = mm;
    }
    __syncthreads();
    float gm = gmaxs[b];
    float s = 0.f;
    for (int i = p; i < NBLK; i += 8)
        s += g_psum[i * B + b] * __expf(g_pmax[i * B + b] - gm);
    ssum[b][p] = s;
    __syncthreads();
    if (t < B) {
        float ss = 0.f;
        #pragma unroll
        for (int q = 0; q < 8; ++q) ss += ssum[t][q];
        lses[t] = gmaxs[t] + logf(ss);
    }
    red[t] = (t < NBLK) ? g_pg[t] : 0.f;
    __syncthreads();
    for (int off = 128; off; off >>= 1) {
        if (t < off) red[t] += red[t + off];
        __syncthreads();
    }
    if (t == 0) {
        float L = 0.f;
        #pragma unroll
        for (int bb = 0; bb < B; ++bb) L += lses[bb];
        out[0] = L / (float)B - red[0] / (float)(B * SEQ);
    }
}

// =========================== launch ======================================
extern "C" void kernel_launch(void* const* d_in, const int* in_sizes, int n_in,
                              void* d_out, int out_size)
{
    // Map inputs robustly by element count (all counts are distinct).
    const float* z = nullptr; const void* labels = nullptr;
    const float* W0 = nullptr; const float* b0 = nullptr;
    const float* W1 = nullptr; const float* b1 = nullptr;
    for (int i = 0; i < n_in; ++i) {
        switch (in_sizes[i]) {
            case B * D:        z      = (const float*)d_in[i];      break; // 32768
            case B * SEQ:      labels = d_in[i];                    break; // 4096
            case D * D:        W0     = (const float*)d_in[i];      break; // 1048576
            case D:            b0     = (const float*)d_in[i];      break; // 1024
            case D * VOCAB:    W1     = (const float*)d_in[i];      break; // 51463168
            case VOCAB:        b1     = (const float*)d_in[i];      break; // 50257
            default: break;
        }
    }

    static bool attr_done = false;
    if (!attr_done) {
        cudaFuncSetAttribute(big_kernel,
                             cudaFuncAttributeMaxDynamicSharedMemorySize,
                             D * B * sizeof(float));
        attr_done = true;
    }

    detect_labels<<<1, 256>>>((const long long*)labels);
    g1_stage1<<<256, 256>>>(z, W0);
    g1_stage2<<<128, 256>>>(b0);
    big_kernel<<<NBLK, 256, D * B * sizeof(float)>>>(W1, b1, labels);
    finalize<<<1, 256>>>((float*)d_out);
}

// round 3
// speedup vs baseline: 1.5187x; 1.5187x over previous
#include <cuda_runtime.h>
#include <cuda_bf16.h>
#include <math.h>

// Problem constants (fixed by the reference)
#define B       32
#define D       1024
#define VOCAB   50257
#define SEQ     128

// GEMM2 tiling
#define VLANES  128        // v-lanes per block
#define VT      3          // v columns per thread
#define VBLK    (VLANES*VT)   // 384 v per block
#define NBLK    ((VOCAB + VBLK - 1) / VBLK)   // 131
#define LSS     385        // logits smem stride (padded)
#define THR     512        // threads in big_kernel
#define CH      8          // k prefetch chunk
#define NCH     (D / CH)   // 128 chunks

// GEMM1 k-split
#define KSPLIT  8

typedef unsigned long long ull;

// ---------------- device scratch (no allocations allowed) ----------------
__device__ float g_hT[D * B];                  // h transposed: [k][b], 128KB
__device__ float g_part[KSPLIT * B * D];       // GEMM1 partials, 1MB
__device__ float g_pmax[NBLK * B];
__device__ float g_psum[NBLK * B];
__device__ float g_pg[NBLK];
__device__ int   g_lab64;                      // 1 if labels are int64

__device__ __forceinline__ void ffma2(ull &acc, ull a, ull b) {
    asm("fma.rn.f32x2 %0, %1, %2, %0;" : "+l"(acc) : "l"(a), "l"(b));
}
__device__ __forceinline__ ull pack2(float w) {
    ull r; asm("mov.b64 %0, {%1, %1};" : "=l"(r) : "f"(w)); return r;
}
__device__ __forceinline__ void unpack2(ull v, float &lo, float &hi) {
    asm("mov.b64 {%0, %1}, %2;" : "=f"(lo), "=f"(hi) : "l"(v));
}

// ================= GEMM1 stage 1: partial z@W0 over a k-slice =============
// grid: 256 blocks = 32 j-tiles (32 cols) x 8 k-slices (128 k each), 256 thr
__global__ __launch_bounds__(256, 2) void g1_stage1(
    const float* __restrict__ z, const float* __restrict__ W0)
{
    __shared__ __align__(16) float zs[128 * 34];   // zT slice [kk][b], padded
    const int jt = blockIdx.x & 31;
    const int ks = blockIdx.x >> 5;
    const int j0 = jt * 32;
    const int k0 = ks * 128;
    const int t  = threadIdx.x;

    for (int i = t; i < B * 128; i += 256) {
        int bb = i >> 7, kk = i & 127;
        zs[kk * 34 + bb] = z[bb * D + k0 + kk];
    }
    __syncthreads();

    const int lane = t & 31;           // j within tile
    const int grp  = t >> 5;           // 8 groups of 4 b
    const int j    = j0 + lane;
    const int b0   = grp * 4;

    ull a0 = 0ull, a1 = 0ull;
    const ull* zs64 = (const ull*)zs;
    const float* pw = W0 + (size_t)k0 * D + j;

    #pragma unroll 8
    for (int kk = 0; kk < 128; ++kk) {
        float w = pw[kk * D];
        ull w2 = pack2(w);
        ull h0 = zs64[kk * 17 + (b0 >> 1)];
        ull h1 = zs64[kk * 17 + (b0 >> 1) + 1];
        ffma2(a0, h0, w2);
        ffma2(a1, h1, w2);
    }
    float f0, f1, f2, f3;
    unpack2(a0, f0, f1);
    unpack2(a1, f2, f3);
    float* dst = g_part + (size_t)ks * (B * D) + b0 * D + j;
    dst[0]      = f0;
    dst[D]      = f1;
    dst[2 * D]  = f2;
    dst[3 * D]  = f3;
}

// ===== GEMM1 stage 2: reduce k-splits, +bias, exact GELU (+ label probe) ==
// grid: 128 x 256. Block 0 additionally probes label dtype (int64 vs int32,
// JAX x64-off silently gives int32): interpret first 2048 8B words as int64;
// int32 labels fuse pairs -> high word nonzero -> out of [0, VOCAB).
__global__ void g1_stage2(const float* __restrict__ b0v,
                          const long long* __restrict__ labels)
{
    if (blockIdx.x == 0) {
        __shared__ int bad;
        if (threadIdx.x == 0) bad = 0;
        __syncthreads();
        for (int i = threadIdx.x; i < 2048; i += 256) {
            long long v = labels[i];
            if (v < 0 || v >= (long long)VOCAB) bad = 1;
        }
        __syncthreads();
        if (threadIdx.x == 0) g_lab64 = bad ? 0 : 1;
    }

    int idx = blockIdx.x * 256 + threadIdx.x;   // 0..32767
    int bb = idx >> 10;
    int j  = idx & 1023;
    float s = b0v[j];
    #pragma unroll
    for (int ks = 0; ks < KSPLIT; ++ks)
        s += g_part[(size_t)ks * (B * D) + bb * D + j];
    float gel = 0.5f * s * (1.0f + erff(s * 0.70710678118654752f));
    g_hT[j * B + bb] = gel;     // transposed for GEMM2 smem broadcast pairs
}

// ======= GEMM2 + bias + partial logsumexp + label gather (the big one) ====
// grid: NBLK=131 blocks, 512 threads, 128KB dynamic smem for hT.
// Mainloop: register double-buffered W1 prefetch (chunks of CH=8 k), so 24
// LDGs are always in flight per warp while FFMA2s drain the previous chunk.
__global__ __launch_bounds__(THR, 1) void big_kernel(
    const float* __restrict__ W1, const float* __restrict__ b1,
    const void* __restrict__ labels)
{
    extern __shared__ __align__(16) float hs[];    // [k][b] = 32768 floats
    const int t = threadIdx.x;

    for (int i = t; i < D * B; i += THR) hs[i] = g_hT[i];
    __syncthreads();

    const int vl    = t & 127;
    const int grp   = t >> 7;          // 4 groups of 8 b
    const int b0    = grp * 8;
    const int hbase = grp * 4;         // pair-index base into hs64 rows
    const int vbase = blockIdx.x * VBLK;

    int  v[VT]; int vc[VT]; bool val[VT];
    #pragma unroll
    for (int j = 0; j < VT; ++j) {
        v[j]   = vbase + vl + 128 * j;
        val[j] = (v[j] < VOCAB);
        vc[j]  = val[j] ? v[j] : 0;
    }

    ull acc[4][VT];
    #pragma unroll
    for (int p = 0; p < 4; ++p)
        #pragma unroll
        for (int j = 0; j < VT; ++j) acc[p][j] = 0ull;

    const ull* hs64 = (const ull*)hs;

    // Double-buffered weight registers: wa = even chunks, wb = odd chunks.
    float wa[CH][VT], wb[CH][VT];

    // preload chunk 0 into wa
    {
        const float* q0 = W1 + vc[0];
        const float* q1 = W1 + vc[1];
        const float* q2 = W1 + vc[2];
        #pragma unroll
        for (int kk = 0; kk < CH; ++kk) {
            wa[kk][0] = q0[(size_t)kk * VOCAB];
            wa[kk][1] = q1[(size_t)kk * VOCAB];
            wa[kk][2] = q2[(size_t)kk * VOCAB];
        }
    }

    for (int c = 0; c < NCH; c += 2) {
        // ---- load chunk c+1 -> wb (c+1 < NCH always since NCH even) ----
        {
            const size_t off = (size_t)(c + 1) * CH * VOCAB;
            const float* q0 = W1 + off + vc[0];
            const float* q1 = W1 + off + vc[1];
            const float* q2 = W1 + off + vc[2];
            #pragma unroll
            for (int kk = 0; kk < CH; ++kk) {
                wb[kk][0] = q0[(size_t)kk * VOCAB];
                wb[kk][1] = q1[(size_t)kk * VOCAB];
                wb[kk][2] = q2[(size_t)kk * VOCAB];
            }
        }
        // ---- compute chunk c from wa ----
        #pragma unroll
        for (int kk = 0; kk < CH; ++kk) {
            const int k = c * CH + kk;
            ull W0p = pack2(wa[kk][0]);
            ull W1p = pack2(wa[kk][1]);
            ull W2p = pack2(wa[kk][2]);
            ull hp[4];
            #pragma unroll
            for (int p = 0; p < 4; ++p) hp[p] = hs64[k * 16 + hbase + p];
            #pragma unroll
            for (int p = 0; p < 4; ++p) {
                ffma2(acc[p][0], hp[p], W0p);
                ffma2(acc[p][1], hp[p], W1p);
                ffma2(acc[p][2], hp[p], W2p);
            }
        }
        // ---- load chunk c+2 -> wa (clamp to 0 on the final wrap) ----
        {
            const int cc = (c + 2 < NCH) ? (c + 2) : 0;
            const size_t off = (size_t)cc * CH * VOCAB;
            const float* q0 = W1 + off + vc[0];
            const float* q1 = W1 + off + vc[1];
            const float* q2 = W1 + off + vc[2];
            #pragma unroll
            for (int kk = 0; kk < CH; ++kk) {
                wa[kk][0] = q0[(size_t)kk * VOCAB];
                wa[kk][1] = q1[(size_t)kk * VOCAB];
                wa[kk][2] = q2[(size_t)kk * VOCAB];
            }
        }
        // ---- compute chunk c+1 from wb ----
        #pragma unroll
        for (int kk = 0; kk < CH; ++kk) {
            const int k = (c + 1) * CH + kk;
            ull W0p = pack2(wb[kk][0]);
            ull W1p = pack2(wb[kk][1]);
            ull W2p = pack2(wb[kk][2]);
            ull hp[4];
            #pragma unroll
            for (int p = 0; p < 4; ++p) hp[p] = hs64[k * 16 + hbase + p];
            #pragma unroll
            for (int p = 0; p < 4; ++p) {
                ffma2(acc[p][0], hp[p], W0p);
                ffma2(acc[p][1], hp[p], W1p);
                ffma2(acc[p][2], hp[p], W2p);
            }
        }
    }
    __syncthreads();                    // done reading hs; reuse as logits

    float* Ls = hs;                     // [b][LSS], 32*385*4 = 49.3KB < 128KB
    #pragma unroll
    for (int j = 0; j < VT; ++j) {
        const int vloc = vl + 128 * j;
        const float bias = val[j] ? b1[v[j]] : 0.f;
        #pragma unroll
        for (int p = 0; p < 4; ++p) {
            float lo, hi;
            unpack2(acc[p][j], lo, hi);
            float f0 = val[j] ? (lo + bias) : -1e30f;
            float f1 = val[j] ? (hi + bias) : -1e30f;
            Ls[(b0 + 2 * p)     * LSS + vloc] = f0;
            Ls[(b0 + 2 * p + 1) * LSS + vloc] = f1;
        }
    }
    __syncthreads();

    // label gather: sum of logits at labels that fall into this v-tile.
    // dtype of labels resolved at runtime by the probe (int64 vs int32).
    const int lab64 = g_lab64;
    const long long* lab_ll = (const long long*)labels;
    const int*       lab_i  = (const int*)labels;
    float g = 0.f;
    for (int i = t; i < B * SEQ; i += THR) {
        int bb = i >> 7;
        int lab = lab64 ? (int)lab_ll[i] : lab_i[i];
        int rel = lab - vbase;
        if (rel >= 0 && rel < VBLK) g += Ls[bb * LSS + rel];
    }
    __shared__ float red[THR];
    red[t] = g;
    __syncthreads();
    for (int off = THR / 2; off; off >>= 1) {
        if (t < off) red[t] += red[t + off];
        __syncthreads();
    }
    if (t == 0) g_pg[blockIdx.x] = red[0];

    // per-b partial (max, sumexp) over this block's 384 columns
    const int wid = t >> 5, lane = t & 31;
    #pragma unroll
    for (int bi = 0; bi < 2; ++bi) {
        const int bb = wid * 2 + bi;
        float m = -1e30f;
        for (int vv = lane; vv < VBLK; vv += 32)
            m = fmaxf(m, Ls[bb * LSS + vv]);
        #pragma unroll
        for (int o = 16; o; o >>= 1)
            m = fmaxf(m, __shfl_xor_sync(0xffffffffu, m, o));
        float s = 0.f;
        for (int vv = lane; vv < VBLK; vv += 32)
            s += __expf(Ls[bb * LSS + vv] - m);
        #pragma unroll
        for (int o = 16; o; o >>= 1)
            s += __shfl_xor_sync(0xffffffffu, s, o);
        if (lane == 0) {
            g_pmax[blockIdx.x * B + bb] = m;
            g_psum[blockIdx.x * B + bb] = s;
        }
    }
}

// ================= finalize: combine partials into the scalar =============
__global__ void finalize(float* __restrict__ out)
{
    __shared__ float smax[B][8];
    __shared__ float ssum[B][8];
    __shared__ float gmaxs[B];
    __shared__ float lses[B];
    __shared__ float red[256];
    const int t = threadIdx.x;
    const int b = t >> 3, p = t & 7;

    float m = -1e30f;
    for (int i = p; i < NBLK; i += 8) m = fmaxf(m, g_pmax[i * B + b]);
    smax[b][p] = m;
    __syncthreads();
    if (t < B) {
        float mm = -1e30f;
        #pragma unroll
        for (int q = 0; q < 8; ++q) mm = fmaxf(mm, smax[t][q]);
        gmaxs[t] = mm;
    }
    __syncthreads();
    float gm = gmaxs[b];
    float s = 0.f;
    for (int i = p; i < NBLK; i += 8)
        s += g_psum[i * B + b] * __expf(g_pmax[i * B + b] - gm);
    ssum[b][p] = s;
    __syncthreads();
    if (t < B) {
        float ss = 0.f;
        #pragma unroll
        for (int q = 0; q < 8; ++q) ss += ssum[t][q];
        lses[t] = gmaxs[t] + logf(ss);
    }
    red[t] = (t < NBLK) ? g_pg[t] : 0.f;
    __syncthreads();
    for (int off = 128; off; off >>= 1) {
        if (t < off) red[t] += red[t + off];
        __syncthreads();
    }
    if (t == 0) {
        float L = 0.f;
        #pragma unroll
        for (int bb = 0; bb < B; ++bb) L += lses[bb];
        out[0] = L / (float)B - red[0] / (float)(B * SEQ);
    }
}

// =========================== launch ======================================
extern "C" void kernel_launch(void* const* d_in, const int* in_sizes, int n_in,
                              void* d_out, int out_size)
{
    // Map inputs robustly by element count (all counts are distinct).
    const float* z = nullptr; const void* labels = nullptr;
    const float* W0 = nullptr; const float* b0 = nullptr;
    const float* W1 = nullptr; const float* b1 = nullptr;
    for (int i = 0; i < n_in; ++i) {
        switch (in_sizes[i]) {
            case B * D:        z      = (const float*)d_in[i];      break; // 32768
            case B * SEQ:      labels = d_in[i];                    break; // 4096
            case D * D:        W0     = (const float*)d_in[i];      break; // 1048576
            case D:            b0     = (const float*)d_in[i];      break; // 1024
            case D * VOCAB:    W1     = (const float*)d_in[i];      break; // 51463168
            case VOCAB:        b1     = (const float*)d_in[i];      break; // 50257
            default: break;
        }
    }

    static bool attr_done = false;
    if (!attr_done) {
        cudaFuncSetAttribute(big_kernel,
                             cudaFuncAttributeMaxDynamicSharedMemorySize,
                             D * B * sizeof(float));
        attr_done = true;
    }

    g1_stage1<<<256, 256>>>(z, W0);
    g1_stage2<<<128, 256>>>(b0, (const long long*)labels);
    big_kernel<<<NBLK, THR, D * B * sizeof(float)>>>(W1, b1, labels);
    finalize<<<1, 256>>>((float*)d_out);
}

// round 4
// speedup vs baseline: 1.5407x; 1.0145x over previous
#include <cuda_runtime.h>
#include <cuda_bf16.h>
#include <math.h>

// Problem constants (fixed by the reference)
#define B       32
#define D       1024
#define VOCAB   50257
#define SEQ     128

// GEMM2 tiling
#define VLANES  128        // v-lanes per block
#define VT      3          // v columns per thread
#define VBLK    (VLANES*VT)   // 384 v per block
#define NBLK    ((VOCAB + VBLK - 1) / VBLK)   // 131
#define LSS     385        // logits smem stride (padded)
#define THR     512        // threads in big_kernel
#define CH      8          // k prefetch chunk
#define NCH     (D / CH)   // 128 chunks

// GEMM1 k-split
#define KSPLIT  8

typedef unsigned long long ull;

// ---------------- device scratch (no allocations allowed) ----------------
__device__ float g_hT[D * B];                  // h transposed: [k][b], 128KB
__device__ float g_part[KSPLIT * B * D];       // GEMM1 partials, 1MB
__device__ float g_pmax[NBLK * B];
__device__ float g_psum[NBLK * B];
__device__ float g_pg[NBLK];
__device__ int   g_lab64;                      // 1 if labels are int64
__device__ int   g_ctr;                        // finalize ticket (self-resets)

__device__ __forceinline__ void ffma2(ull &acc, ull a, ull b) {
    asm("fma.rn.f32x2 %0, %1, %2, %0;" : "+l"(acc) : "l"(a), "l"(b));
}
__device__ __forceinline__ ull pack2(float w) {
    ull r; asm("mov.b64 %0, {%1, %1};" : "=l"(r) : "f"(w)); return r;
}
__device__ __forceinline__ void unpack2(ull v, float &lo, float &hi) {
    asm("mov.b64 {%0, %1}, %2;" : "=f"(lo), "=f"(hi) : "l"(v));
}

// ================= GEMM1 stage 1: partial z@W0 over a k-slice =============
// grid: 256 blocks = 32 j-tiles (32 cols) x 8 k-slices (128 k each), 256 thr
__global__ __launch_bounds__(256, 2) void g1_stage1(
    const float* __restrict__ z, const float* __restrict__ W0)
{
    __shared__ __align__(16) float zs[128 * 34];   // zT slice [kk][b], padded
    const int jt = blockIdx.x & 31;
    const int ks = blockIdx.x >> 5;
    const int j0 = jt * 32;
    const int k0 = ks * 128;
    const int t  = threadIdx.x;

    for (int i = t; i < B * 128; i += 256) {
        int bb = i >> 7, kk = i & 127;
        zs[kk * 34 + bb] = z[bb * D + k0 + kk];
    }
    __syncthreads();

    const int lane = t & 31;           // j within tile
    const int grp  = t >> 5;           // 8 groups of 4 b
    const int j    = j0 + lane;
    const int b0   = grp * 4;

    ull a0 = 0ull, a1 = 0ull;
    const ull* zs64 = (const ull*)zs;
    const float* pw = W0 + (size_t)k0 * D + j;

    #pragma unroll 8
    for (int kk = 0; kk < 128; ++kk) {
        float w = pw[kk * D];
        ull w2 = pack2(w);
        ull h0 = zs64[kk * 17 + (b0 >> 1)];
        ull h1 = zs64[kk * 17 + (b0 >> 1) + 1];
        ffma2(a0, h0, w2);
        ffma2(a1, h1, w2);
    }
    float f0, f1, f2, f3;
    unpack2(a0, f0, f1);
    unpack2(a1, f2, f3);
    float* dst = g_part + (size_t)ks * (B * D) + b0 * D + j;
    dst[0]      = f0;
    dst[D]      = f1;
    dst[2 * D]  = f2;
    dst[3 * D]  = f3;
}

// ===== GEMM1 stage 2: reduce k-splits, +bias, exact GELU (+ label probe) ==
// grid: 128 x 256. Block 0 additionally probes label dtype (int64 vs int32,
// JAX x64-off silently gives int32): interpret first 2048 8B words as int64;
// int32 labels fuse pairs -> high word nonzero -> out of [0, VOCAB).
__global__ void g1_stage2(const float* __restrict__ b0v,
                          const long long* __restrict__ labels)
{
    if (blockIdx.x == 0) {
        __shared__ int bad;
        if (threadIdx.x == 0) bad = 0;
        __syncthreads();
        for (int i = threadIdx.x; i < 2048; i += 256) {
            long long v = labels[i];
            if (v < 0 || v >= (long long)VOCAB) bad = 1;
        }
        __syncthreads();
        if (threadIdx.x == 0) g_lab64 = bad ? 0 : 1;
    }

    int idx = blockIdx.x * 256 + threadIdx.x;   // 0..32767
    int bb = idx >> 10;
    int j  = idx & 1023;
    float s = b0v[j];
    #pragma unroll
    for (int ks = 0; ks < KSPLIT; ++ks)
        s += g_part[(size_t)ks * (B * D) + bb * D + j];
    float gel = 0.5f * s * (1.0f + erff(s * 0.70710678118654752f));
    g_hT[j * B + bb] = gel;     // transposed for GEMM2 smem broadcast pairs
}

// ======= GEMM2 + bias + logsumexp + label gather + fused finalize =========
// grid: NBLK=131 blocks, 512 threads, 128KB dynamic smem for hT.
// Mainloop: register double-buffered W1 prefetch (chunks of CH=8 k); h pairs
// loaded as 2x LDS.128. Last block (atomic ticket) folds the final reduction.
__global__ __launch_bounds__(THR, 1) void big_kernel(
    const float* __restrict__ W1, const float* __restrict__ b1,
    const void* __restrict__ labels, float* __restrict__ out)
{
    extern __shared__ __align__(16) float hs[];    // [k][b] = 32768 floats
    const int t = threadIdx.x;

    for (int i = t; i < D * B; i += THR) hs[i] = g_hT[i];
    __syncthreads();

    const int vl    = t & 127;
    const int grp   = t >> 7;          // 4 groups of 8 b
    const int b0    = grp * 8;
    const int hb2   = grp * 2;         // ulonglong2 index base within k-row
    const int vbase = blockIdx.x * VBLK;

    int  v[VT]; int vc[VT]; bool val[VT];
    #pragma unroll
    for (int j = 0; j < VT; ++j) {
        v[j]   = vbase + vl + 128 * j;
        val[j] = (v[j] < VOCAB);
        vc[j]  = val[j] ? v[j] : 0;
    }

    ull acc[4][VT];
    #pragma unroll
    for (int p = 0; p < 4; ++p)
        #pragma unroll
        for (int j = 0; j < VT; ++j) acc[p][j] = 0ull;

    const ulonglong2* hs128 = (const ulonglong2*)hs;  // 8 entries per k-row

    // Double-buffered weight registers: wa = even chunks, wb = odd chunks.
    float wa[CH][VT], wb[CH][VT];

    // preload chunk 0 into wa
    {
        const float* q0 = W1 + vc[0];
        const float* q1 = W1 + vc[1];
        const float* q2 = W1 + vc[2];
        #pragma unroll
        for (int kk = 0; kk < CH; ++kk) {
            wa[kk][0] = q0[(size_t)kk * VOCAB];
            wa[kk][1] = q1[(size_t)kk * VOCAB];
            wa[kk][2] = q2[(size_t)kk * VOCAB];
        }
    }

    for (int c = 0; c < NCH; c += 2) {
        // ---- load chunk c+1 -> wb ----
        {
            const size_t off = (size_t)(c + 1) * CH * VOCAB;
            const float* q0 = W1 + off + vc[0];
            const float* q1 = W1 + off + vc[1];
            const float* q2 = W1 + off + vc[2];
            #pragma unroll
            for (int kk = 0; kk < CH; ++kk) {
                wb[kk][0] = q0[(size_t)kk * VOCAB];
                wb[kk][1] = q1[(size_t)kk * VOCAB];
                wb[kk][2] = q2[(size_t)kk * VOCAB];
            }
        }
        // ---- compute chunk c from wa ----
        #pragma unroll
        for (int kk = 0; kk < CH; ++kk) {
            const int k = c * CH + kk;
            ull W0p = pack2(wa[kk][0]);
            ull W1p = pack2(wa[kk][1]);
            ull W2p = pack2(wa[kk][2]);
            ulonglong2 ha = hs128[k * 8 + hb2];
            ulonglong2 hbv = hs128[k * 8 + hb2 + 1];
            ffma2(acc[0][0], ha.x, W0p);  ffma2(acc[0][1], ha.x, W1p);  ffma2(acc[0][2], ha.x, W2p);
            ffma2(acc[1][0], ha.y, W0p);  ffma2(acc[1][1], ha.y, W1p);  ffma2(acc[1][2], ha.y, W2p);
            ffma2(acc[2][0], hbv.x, W0p); ffma2(acc[2][1], hbv.x, W1p); ffma2(acc[2][2], hbv.x, W2p);
            ffma2(acc[3][0], hbv.y, W0p); ffma2(acc[3][1], hbv.y, W1p); ffma2(acc[3][2], hbv.y, W2p);
        }
        // ---- load chunk c+2 -> wa (clamp on the final wrap) ----
        {
            const int cc = (c + 2 < NCH) ? (c + 2) : 0;
            const size_t off = (size_t)cc * CH * VOCAB;
            const float* q0 = W1 + off + vc[0];
            const float* q1 = W1 + off + vc[1];
            const float* q2 = W1 + off + vc[2];
            #pragma unroll
            for (int kk = 0; kk < CH; ++kk) {
                wa[kk][0] = q0[(size_t)kk * VOCAB];
                wa[kk][1] = q1[(size_t)kk * VOCAB];
                wa[kk][2] = q2[(size_t)kk * VOCAB];
            }
        }
        // ---- compute chunk c+1 from wb ----
        #pragma unroll
        for (int kk = 0; kk < CH; ++kk) {
            const int k = (c + 1) * CH + kk;
            ull W0p = pack2(wb[kk][0]);
            ull W1p = pack2(wb[kk][1]);
            ull W2p = pack2(wb[kk][2]);
            ulonglong2 ha = hs128[k * 8 + hb2];
            ulonglong2 hbv = hs128[k * 8 + hb2 + 1];
            ffma2(acc[0][0], ha.x, W0p);  ffma2(acc[0][1], ha.x, W1p);  ffma2(acc[0][2], ha.x, W2p);
            ffma2(acc[1][0], ha.y, W0p);  ffma2(acc[1][1], ha.y, W1p);  ffma2(acc[1][2], ha.y, W2p);
            ffma2(acc[2][0], hbv.x, W0p); ffma2(acc[2][1], hbv.x, W1p); ffma2(acc[2][2], hbv.x, W2p);
            ffma2(acc[3][0], hbv.y, W0p); ffma2(acc[3][1], hbv.y, W1p); ffma2(acc[3][2], hbv.y, W2p);
        }
    }
    __syncthreads();                    // done reading hs; reuse as logits

    float* Ls = hs;                     // [b][LSS], 32*385*4 = 49.3KB < 128KB
    #pragma unroll
    for (int j = 0; j < VT; ++j) {
        const int vloc = vl + 128 * j;
        const float bias = val[j] ? b1[v[j]] : 0.f;
        #pragma unroll
        for (int p = 0; p < 4; ++p) {
            float lo, hi;
            unpack2(acc[p][j], lo, hi);
            float f0 = val[j] ? (lo + bias) : -1e30f;
            float f1 = val[j] ? (hi + bias) : -1e30f;
            Ls[(b0 + 2 * p)     * LSS + vloc] = f0;
            Ls[(b0 + 2 * p + 1) * LSS + vloc] = f1;
        }
    }
    __syncthreads();

    // label gather: sum of logits at labels that fall into this v-tile.
    const int lab64 = g_lab64;
    const long long* lab_ll = (const long long*)labels;
    const int*       lab_i  = (const int*)labels;
    float g = 0.f;
    for (int i = t; i < B * SEQ; i += THR) {
        int bb = i >> 7;
        int lab = lab64 ? (int)lab_ll[i] : lab_i[i];
        int rel = lab - vbase;
        if (rel >= 0 && rel < VBLK) g += Ls[bb * LSS + rel];
    }
    __shared__ float red[THR];
    red[t] = g;
    __syncthreads();
    for (int off = THR / 2; off; off >>= 1) {
        if (t < off) red[t] += red[t + off];
        __syncthreads();
    }
    if (t == 0) g_pg[blockIdx.x] = red[0];

    // per-b partial (max, sumexp) over this block's 384 columns
    const int wid = t >> 5, lane = t & 31;
    #pragma unroll
    for (int bi = 0; bi < 2; ++bi) {
        const int bb = wid * 2 + bi;
        float m = -1e30f;
        for (int vv = lane; vv < VBLK; vv += 32)
            m = fmaxf(m, Ls[bb * LSS + vv]);
        #pragma unroll
        for (int o = 16; o; o >>= 1)
            m = fmaxf(m, __shfl_xor_sync(0xffffffffu, m, o));
        float s = 0.f;
        for (int vv = lane; vv < VBLK; vv += 32)
            s += __expf(Ls[bb * LSS + vv] - m);
        #pragma unroll
        for (int o = 16; o; o >>= 1)
            s += __shfl_xor_sync(0xffffffffu, s, o);
        if (lane == 0) {
            g_pmax[blockIdx.x * B + bb] = m;
            g_psum[blockIdx.x * B + bb] = s;
        }
    }

    // ---- fused finalize: last block to arrive reduces all partials ----
    __threadfence();
    __syncthreads();
    __shared__ int is_last;
    if (t == 0) {
        int old = atomicAdd(&g_ctr, 1);
        is_last = (old == NBLK - 1);
    }
    __syncthreads();
    if (!is_last) return;
    __threadfence();

    __shared__ float s_lse[B];
    #pragma unroll
    for (int bi = 0; bi < 2; ++bi) {
        const int bb = wid * 2 + bi;
        float m = -1e30f;
        for (int i = lane; i < NBLK; i += 32)
            m = fmaxf(m, g_pmax[i * B + bb]);
        #pragma unroll
        for (int o = 16; o; o >>= 1)
            m = fmaxf(m, __shfl_xor_sync(0xffffffffu, m, o));
        float s = 0.f;
        for (int i = lane; i < NBLK; i += 32)
            s += g_psum[i * B + bb] * __expf(g_pmax[i * B + bb] - m);
        #pragma unroll
        for (int o = 16; o; o >>= 1)
            s += __shfl_xor_sync(0xffffffffu, s, o);
        if (lane == 0) s_lse[bb] = m + logf(s);
    }
    float gg = (t < NBLK) ? g_pg[t] : 0.f;
    red[t] = gg;
    __syncthreads();
    for (int off = THR / 2; off; off >>= 1) {
        if (t < off) red[t] += red[t + off];
        __syncthreads();
    }
    if (t == 0) {
        float L = 0.f;
        #pragma unroll
        for (int bb = 0; bb < B; ++bb) L += s_lse[bb];
        out[0] = L / (float)B - red[0] / (float)(B * SEQ);
        g_ctr = 0;                      // reset for next graph replay
    }
}

// =========================== launch ======================================
extern "C" void kernel_launch(void* const* d_in, const int* in_sizes, int n_in,
                              void* d_out, int out_size)
{
    // Map inputs robustly by element count (all counts are distinct).
    const float* z = nullptr; const void* labels = nullptr;
    const float* W0 = nullptr; const float* b0 = nullptr;
    const float* W1 = nullptr; const float* b1 = nullptr;
    for (int i = 0; i < n_in; ++i) {
        switch (in_sizes[i]) {
            case B * D:        z      = (const float*)d_in[i];      break; // 32768
            case B * SEQ:      labels = d_in[i];                    break; // 4096
            case D * D:        W0     = (const float*)d_in[i];      break; // 1048576
            case D:            b0     = (const float*)d_in[i];      break; // 1024
            case D * VOCAB:    W1     = (const float*)d_in[i];      break; // 51463168
            case VOCAB:        b1     = (const float*)d_in[i];      break; // 50257
            default: break;
        }
    }

    static bool attr_done = false;
    if (!attr_done) {
        cudaFuncSetAttribute(big_kernel,
                             cudaFuncAttributeMaxDynamicSharedMemorySize,
                             D * B * sizeof(float));
        attr_done = true;
    }

    g1_stage1<<<256, 256>>>(z, W0);
    g1_stage2<<<128, 256>>>(b0, (const long long*)labels);
    big_kernel<<<NBLK, THR, D * B * sizeof(float)>>>(W1, b1, labels,
                                                     (float*)d_out);
}

// round 5
// speedup vs baseline: 1.6376x; 1.0629x over previous
#include <cuda_runtime.h>
#include <cuda_bf16.h>
#include <math.h>

// Problem constants (fixed by the reference)
#define B       32
#define D       1024
#define VOCAB   50257
#define SEQ     128

// GEMM2 tiling
#define VLANES  128        // v-lanes per block
#define VT      3          // v columns per thread
#define VBLK    (VLANES*VT)   // 384 v per block
#define NBLK    ((VOCAB + VBLK - 1) / VBLK)   // 131
#define LSS     385        // logits smem stride (padded)
#define THR     512        // threads in big_kernel
#define CH      4          // k prefetch chunk (quad-buffered, distance 2)
#define NCH     (D / CH)   // 256 chunks

// GEMM1 k-split
#define KSPLIT  16

typedef unsigned long long ull;

// ---------------- device scratch (no allocations allowed) ----------------
__device__ float g_hT[D * B];                  // h transposed: [k][b], 128KB
__device__ float g_part[KSPLIT * B * D];       // GEMM1 partials, 2MB
__device__ float g_pmax[NBLK * B];
__device__ float g_psum[NBLK * B];
__device__ float g_pg[NBLK];
__device__ int   g_lab64;                      // 1 if labels are int64
__device__ int   g_ctr;                        // finalize ticket (self-resets)

__device__ __forceinline__ void ffma2(ull &acc, ull a, ull b) {
    asm("fma.rn.f32x2 %0, %1, %2, %0;" : "+l"(acc) : "l"(a), "l"(b));
}
__device__ __forceinline__ ull pack2(float w) {
    ull r; asm("mov.b64 %0, {%1, %1};" : "=l"(r) : "f"(w)); return r;
}
__device__ __forceinline__ void unpack2(ull v, float &lo, float &hi) {
    asm("mov.b64 {%0, %1}, %2;" : "=f"(lo), "=f"(hi) : "l"(v));
}

// ================= GEMM1 stage 1: partial z@W0 over a k-slice =============
// grid: 512 blocks = 32 j-tiles (32 cols) x 16 k-slices (64 k each), 256 thr
__global__ __launch_bounds__(256, 4) void g1_stage1(
    const float* __restrict__ z, const float* __restrict__ W0)
{
    __shared__ __align__(16) float zs[64 * 34];    // zT slice [kk][b], padded
    const int jt = blockIdx.x & 31;
    const int ks = blockIdx.x >> 5;
    const int j0 = jt * 32;
    const int k0 = ks * 64;
    const int t  = threadIdx.x;

    for (int i = t; i < B * 64; i += 256) {
        int bb = i >> 6, kk = i & 63;
        zs[kk * 34 + bb] = z[bb * D + k0 + kk];
    }
    __syncthreads();

    const int lane = t & 31;           // j within tile
    const int grp  = t >> 5;           // 8 groups of 4 b
    const int j    = j0 + lane;
    const int b0   = grp * 4;

    ull a0 = 0ull, a1 = 0ull;
    const ull* zs64 = (const ull*)zs;
    const float* pw = W0 + (size_t)k0 * D + j;

    #pragma unroll 16
    for (int kk = 0; kk < 64; ++kk) {
        float w = pw[kk * D];
        ull w2 = pack2(w);
        ull h0 = zs64[kk * 17 + (b0 >> 1)];
        ull h1 = zs64[kk * 17 + (b0 >> 1) + 1];
        ffma2(a0, h0, w2);
        ffma2(a1, h1, w2);
    }
    float f0, f1, f2, f3;
    unpack2(a0, f0, f1);
    unpack2(a1, f2, f3);
    float* dst = g_part + (size_t)ks * (B * D) + b0 * D + j;
    dst[0]      = f0;
    dst[D]      = f1;
    dst[2 * D]  = f2;
    dst[3 * D]  = f3;
}

// ===== GEMM1 stage 2: reduce k-splits, +bias, exact GELU (+ label probe) ==
__global__ void g1_stage2(const float* __restrict__ b0v,
                          const long long* __restrict__ labels)
{
    if (blockIdx.x == 0) {
        __shared__ int bad;
        if (threadIdx.x == 0) bad = 0;
        __syncthreads();
        for (int i = threadIdx.x; i < 2048; i += 256) {
            long long v = labels[i];
            if (v < 0 || v >= (long long)VOCAB) bad = 1;
        }
        __syncthreads();
        if (threadIdx.x == 0) g_lab64 = bad ? 0 : 1;
    }

    int idx = blockIdx.x * 256 + threadIdx.x;   // 0..32767
    int bb = idx >> 10;
    int j  = idx & 1023;
    float s = b0v[j];
    #pragma unroll
    for (int ks = 0; ks < KSPLIT; ++ks)
        s += g_part[(size_t)ks * (B * D) + bb * D + j];
    float gel = 0.5f * s * (1.0f + erff(s * 0.70710678118654752f));
    g_hT[j * B + bb] = gel;     // transposed for GEMM2 smem broadcast pairs
}

// ======= GEMM2 + bias + logsumexp + label gather + fused finalize =========
// grid: NBLK=131 blocks, 512 threads, 128KB dynamic smem for hT.
// Mainloop: quad-buffered W1 register prefetch (CH=4 k per chunk, loads
// issued 2 chunks ahead ~768cyc > DRAM latency). h pairs via 4x LDS.64.
__global__ __launch_bounds__(THR, 1) void big_kernel(
    const float* __restrict__ W1, const float* __restrict__ b1,
    const void* __restrict__ labels, float* __restrict__ out)
{
    extern __shared__ __align__(16) float hs[];    // [k][b] = 32768 floats
    const int t = threadIdx.x;

    for (int i = t; i < D * B; i += THR) hs[i] = g_hT[i];
    __syncthreads();

    const int vl    = t & 127;
    const int grp   = t >> 7;          // 4 groups of 8 b
    const int b0    = grp * 8;
    const int hbase = grp * 4;         // ull pair-index base within k-row
    const int vbase = blockIdx.x * VBLK;

    int  v[VT]; int vc[VT]; bool val[VT];
    #pragma unroll
    for (int j = 0; j < VT; ++j) {
        v[j]   = vbase + vl + 128 * j;
        val[j] = (v[j] < VOCAB);
        vc[j]  = val[j] ? v[j] : 0;
    }

    ull acc[4][VT];
    #pragma unroll
    for (int p = 0; p < 4; ++p)
        #pragma unroll
        for (int j = 0; j < VT; ++j) acc[p][j] = 0ull;

    const ull* hs64 = (const ull*)hs;

    // Quad-buffered weight registers, prefetch distance 2 chunks.
    float w0b[CH][VT], w1b[CH][VT], w2b[CH][VT], w3b[CH][VT];

#define LOADCHUNK(BUF, CIDX) do {                                          \
        const size_t off_ = (size_t)(CIDX) * CH * VOCAB;                   \
        const float* q0_ = W1 + off_ + vc[0];                              \
        const float* q1_ = W1 + off_ + vc[1];                              \
        const float* q2_ = W1 + off_ + vc[2];                              \
        _Pragma("unroll")                                                  \
        for (int kk_ = 0; kk_ < CH; ++kk_) {                               \
            BUF[kk_][0] = q0_[(size_t)kk_ * VOCAB];                        \
            BUF[kk_][1] = q1_[(size_t)kk_ * VOCAB];                        \
            BUF[kk_][2] = q2_[(size_t)kk_ * VOCAB];                        \
        }                                                                  \
    } while (0)

#define COMPCHUNK(BUF, CBASE) do {                                         \
        _Pragma("unroll")                                                  \
        for (int kk_ = 0; kk_ < CH; ++kk_) {                               \
            const int k_ = (CBASE) * CH + kk_;                             \
            ull W0p_ = pack2(BUF[kk_][0]);                                 \
            ull W1p_ = pack2(BUF[kk_][1]);                                 \
            ull W2p_ = pack2(BUF[kk_][2]);                                 \
            ull hp_[4];                                                    \
            _Pragma("unroll")                                              \
            for (int p_ = 0; p_ < 4; ++p_)                                 \
                hp_[p_] = hs64[k_ * 16 + hbase + p_];                      \
            _Pragma("unroll")                                              \
            for (int p_ = 0; p_ < 4; ++p_) {                               \
                ffma2(acc[p_][0], hp_[p_], W0p_);                          \
                ffma2(acc[p_][1], hp_[p_], W1p_);                          \
                ffma2(acc[p_][2], hp_[p_], W2p_);                          \
            }                                                              \
        }                                                                  \
    } while (0)

    LOADCHUNK(w0b, 0);
    LOADCHUNK(w1b, 1);

    for (int c = 0; c < NCH; c += 4) {
        LOADCHUNK(w2b, c + 2);
        COMPCHUNK(w0b, c);
        LOADCHUNK(w3b, c + 3);
        COMPCHUNK(w1b, c + 1);
        { const int cc = (c + 4 < NCH) ? (c + 4) : 0; LOADCHUNK(w0b, cc); }
        COMPCHUNK(w2b, c + 2);
        { const int cc = (c + 5 < NCH) ? (c + 5) : 0; LOADCHUNK(w1b, cc); }
        COMPCHUNK(w3b, c + 3);
    }
    __syncthreads();                    // done reading hs; reuse as logits

    float* Ls = hs;                     // [b][LSS], 32*385*4 = 49.3KB < 128KB
    #pragma unroll
    for (int j = 0; j < VT; ++j) {
        const int vloc = vl + 128 * j;
        const float bias = val[j] ? b1[v[j]] : 0.f;
        #pragma unroll
        for (int p = 0; p < 4; ++p) {
            float lo, hi;
            unpack2(acc[p][j], lo, hi);
            float f0 = val[j] ? (lo + bias) : -1e30f;
            float f1 = val[j] ? (hi + bias) : -1e30f;
            Ls[(b0 + 2 * p)     * LSS + vloc] = f0;
            Ls[(b0 + 2 * p + 1) * LSS + vloc] = f1;
        }
    }
    __syncthreads();

    // label gather: sum of logits at labels that fall into this v-tile.
    const int lab64 = g_lab64;
    const long long* lab_ll = (const long long*)labels;
    const int*       lab_i  = (const int*)labels;
    float g = 0.f;
    for (int i = t; i < B * SEQ; i += THR) {
        int bb = i >> 7;
        int lab = lab64 ? (int)lab_ll[i] : lab_i[i];
        int rel = lab - vbase;
        if (rel >= 0 && rel < VBLK) g += Ls[bb * LSS + rel];
    }
    __shared__ float red[THR];
    red[t] = g;
    __syncthreads();
    for (int off = THR / 2; off; off >>= 1) {
        if (t < off) red[t] += red[t + off];
        __syncthreads();
    }
    if (t == 0) g_pg[blockIdx.x] = red[0];

    // per-b partial (max, sumexp) over this block's 384 columns
    const int wid = t >> 5, lane = t & 31;
    #pragma unroll
    for (int bi = 0; bi < 2; ++bi) {
        const int bb = wid * 2 + bi;
        float m = -1e30f;
        for (int vv = lane; vv < VBLK; vv += 32)
            m = fmaxf(m, Ls[bb * LSS + vv]);
        #pragma unroll
        for (int o = 16; o; o >>= 1)
            m = fmaxf(m, __shfl_xor_sync(0xffffffffu, m, o));
        float s = 0.f;
        for (int vv = lane; vv < VBLK; vv += 32)
            s += __expf(Ls[bb * LSS + vv] - m);
        #pragma unroll
        for (int o = 16; o; o >>= 1)
            s += __shfl_xor_sync(0xffffffffu, s, o);
        if (lane == 0) {
            g_pmax[blockIdx.x * B + bb] = m;
            g_psum[blockIdx.x * B + bb] = s;
        }
    }

    // ---- fused finalize: last block to arrive reduces all partials ----
    __threadfence();
    __syncthreads();
    __shared__ int is_last;
    if (t == 0) {
        int old = atomicAdd(&g_ctr, 1);
        is_last = (old == NBLK - 1);
    }
    __syncthreads();
    if (!is_last) return;
    __threadfence();

    __shared__ float s_lse[B];
    #pragma unroll
    for (int bi = 0; bi < 2; ++bi) {
        const int bb = wid * 2 + bi;
        float m = -1e30f;
        for (int i = lane; i < NBLK; i += 32)
            m = fmaxf(m, g_pmax[i * B + bb]);
        #pragma unroll
        for (int o = 16; o; o >>= 1)
            m = fmaxf(m, __shfl_xor_sync(0xffffffffu, m, o));
        float s = 0.f;
        for (int i = lane; i < NBLK; i += 32)
            s += g_psum[i * B + bb] * __expf(g_pmax[i * B + bb] - m);
        #pragma unroll
        for (int o = 16; o; o >>= 1)
            s += __shfl_xor_sync(0xffffffffu, s, o);
        if (lane == 0) s_lse[bb] = m + logf(s);
    }
    float gg = (t < NBLK) ? g_pg[t] : 0.f;
    red[t] = gg;
    __syncthreads();
    for (int off = THR / 2; off; off >>= 1) {
        if (t < off) red[t] += red[t + off];
        __syncthreads();
    }
    if (t == 0) {
        float L = 0.f;
        #pragma unroll
        for (int bb = 0; bb < B; ++bb) L += s_lse[bb];
        out[0] = L / (float)B - red[0] / (float)(B * SEQ);
        g_ctr = 0;                      // reset for next graph replay
    }
}

// =========================== launch ======================================
extern "C" void kernel_launch(void* const* d_in, const int* in_sizes, int n_in,
                              void* d_out, int out_size)
{
    // Map inputs robustly by element count (all counts are distinct).
    const float* z = nullptr; const void* labels = nullptr;
    const float* W0 = nullptr; const float* b0 = nullptr;
    const float* W1 = nullptr; const float* b1 = nullptr;
    for (int i = 0; i < n_in; ++i) {
        switch (in_sizes[i]) {
            case B * D:        z      = (const float*)d_in[i];      break; // 32768
            case B * SEQ:      labels = d_in[i];                    break; // 4096
            case D * D:        W0     = (const float*)d_in[i];      break; // 1048576
            case D:            b0     = (const float*)d_in[i];      break; // 1024
            case D * VOCAB:    W1     = (const float*)d_in[i];      break; // 51463168
            case VOCAB:        b1     = (const float*)d_in[i];      break; // 50257
            default: break;
        }
    }

    static bool attr_done = false;
    if (!attr_done) {
        cudaFuncSetAttribute(big_kernel,
                             cudaFuncAttributeMaxDynamicSharedMemorySize,
                             D * B * sizeof(float));
        attr_done = true;
    }

    g1_stage1<<<512, 256>>>(z, W0);
    g1_stage2<<<128, 256>>>(b0, (const long long*)labels);
    big_kernel<<<NBLK, THR, D * B * sizeof(float)>>>(W1, b1, labels,
                                                     (float*)d_out);
}

// round 7
// speedup vs baseline: 1.8445x; 1.1264x over previous
#include <cuda_runtime.h>
#include <cuda_bf16.h>
#include <math.h>
#include <stdint.h>

// Problem constants
#define B       32
#define D       1024
#define VOCAB   50257
#define SEQ     128

// GEMM2 tiling (mma.sync m16n8k8 tf32)
#define VBLK    384                        // vocab cols per CTA
#define NBLK    131                        // ceil(50257/384)
#define LSS     385                        // logits smem stride (padded)
#define GT      256                        // threads (8 warps)
#define SK      16                         // k rows per stage
#define NSTG    (D / SK)                   // 64 stages
#define DEPTH   3                          // cp.async pipeline depth
#define ROWP    392                        // padded B smem row (floats)
#define CPR     97                         // 16B chunks per B row (388 floats)
#define HPITCH  1028                       // padded h smem row (floats)
#define HBYTES  (B * HPITCH * 4)           // 131584
#define BSTAGE  (SK * ROWP * 4)            // 25088
#define SMEM_DYN (HBYTES + DEPTH * BSTAGE) // 206848 < 227KB

// GEMM1 k-split
#define KSPLIT  16

typedef unsigned long long ull;

// ---------------- device scratch ----------------
__device__ __align__(16) float g_h[B * D];     // h, tf32-rounded, row-major
__device__ float g_part[KSPLIT * B * D];
__device__ float g_pmax[NBLK * B];
__device__ float g_psum[NBLK * B];
__device__ float g_pg[NBLK];
__device__ int   g_lab64;
__device__ int   g_ctr;

// ---------------- helpers ----------------
__device__ __forceinline__ void ffma2(ull &acc, ull a, ull b) {
    asm("fma.rn.f32x2 %0, %1, %2, %0;" : "+l"(acc) : "l"(a), "l"(b));
}
__device__ __forceinline__ ull pack2(float w) {
    ull r; asm("mov.b64 %0, {%1, %1};" : "=l"(r) : "f"(w)); return r;
}
__device__ __forceinline__ void unpack2(ull v, float &lo, float &hi) {
    asm("mov.b64 {%0, %1}, %2;" : "=f"(lo), "=f"(hi) : "l"(v));
}
__device__ __forceinline__ uint32_t smem_u32(const void* p) {
    uint32_t a;
    asm("{ .reg .u64 t; cvta.to.shared.u64 t, %1; cvt.u32.u64 %0, t; }"
        : "=r"(a) : "l"(p));
    return a;
}
__device__ __forceinline__ uint32_t cvt_tf32(float f) {
    uint32_t r; asm("cvt.rna.tf32.f32 %0, %1;" : "=r"(r) : "f"(f)); return r;
}
__device__ __forceinline__ float lds_f(uint32_t a) {
    float v; asm volatile("ld.shared.f32 %0, [%1];" : "=f"(v) : "r"(a)); return v;
}
__device__ __forceinline__ void mma_tf32(float d[4], const uint32_t a[4],
                                         uint32_t b0, uint32_t b1) {
    asm volatile(
        "mma.sync.aligned.m16n8k8.row.col.f32.tf32.tf32.f32 "
        "{%0,%1,%2,%3}, {%4,%5,%6,%7}, {%8,%9}, {%0,%1,%2,%3};"
        : "+f"(d[0]), "+f"(d[1]), "+f"(d[2]), "+f"(d[3])
        : "r"(a[0]), "r"(a[1]), "r"(a[2]), "r"(a[3]), "r"(b0), "r"(b1));
}
__device__ __forceinline__ void cp16(uint32_t dst, const void* src) {
    asm volatile("cp.async.cg.shared.global [%0], [%1], 16;"
                 :: "r"(dst), "l"(src));
}

// ================= GEMM1 stage 1 (unchanged, proven) ======================
__global__ __launch_bounds__(256, 4) void g1_stage1(
    const float* __restrict__ z, const float* __restrict__ W0)
{
    __shared__ __align__(16) float zs[64 * 34];
    const int jt = blockIdx.x & 31;
    const int ks = blockIdx.x >> 5;
    const int j0 = jt * 32;
    const int k0 = ks * 64;
    const int t  = threadIdx.x;

    for (int i = t; i < B * 64; i += 256) {
        int bb = i >> 6, kk = i & 63;
        zs[kk * 34 + bb] = z[bb * D + k0 + kk];
    }
    __syncthreads();

    const int lane = t & 31;
    const int grp  = t >> 5;
    const int j    = j0 + lane;
    const int b0   = grp * 4;

    ull a0 = 0ull, a1 = 0ull;
    const ull* zs64 = (const ull*)zs;
    const float* pw = W0 + (size_t)k0 * D + j;

    #pragma unroll 16
    for (int kk = 0; kk < 64; ++kk) {
        float w = pw[kk * D];
        ull w2 = pack2(w);
        ull h0 = zs64[kk * 17 + (b0 >> 1)];
        ull h1 = zs64[kk * 17 + (b0 >> 1) + 1];
        ffma2(a0, h0, w2);
        ffma2(a1, h1, w2);
    }
    float f0, f1, f2, f3;
    unpack2(a0, f0, f1);
    unpack2(a1, f2, f3);
    float* dst = g_part + (size_t)ks * (B * D) + b0 * D + j;
    dst[0]      = f0;
    dst[D]      = f1;
    dst[2 * D]  = f2;
    dst[3 * D]  = f3;
}

// ===== GEMM1 stage 2: reduce + GELU -> tf32-rounded h (+ label probe) =====
__global__ void g1_stage2(const float* __restrict__ b0v,
                          const long long* __restrict__ labels)
{
    if (blockIdx.x == 0) {
        __shared__ int bad;
        if (threadIdx.x == 0) bad = 0;
        __syncthreads();
        for (int i = threadIdx.x; i < 2048; i += 256) {
            long long v = labels[i];
            if (v < 0 || v >= (long long)VOCAB) bad = 1;
        }
        __syncthreads();
        if (threadIdx.x == 0) g_lab64 = bad ? 0 : 1;
    }

    int idx = blockIdx.x * 256 + threadIdx.x;   // 0..32767
    int bb = idx >> 10;
    int j  = idx & 1023;
    float s = b0v[j];
    #pragma unroll
    for (int ks = 0; ks < KSPLIT; ++ks)
        s += g_part[(size_t)ks * (B * D) + bb * D + j];
    float gel = 0.5f * s * (1.0f + erff(s * 0.70710678118654752f));
    g_h[bb * D + j] = __uint_as_float(cvt_tf32(gel));
}

// ========== GEMM2: mma.sync tf32 + softmax + fused finalize ===============
// B row k of W1 is 4B-aligned only; since VOCAB % 4 == 1 the misalignment of
// (k*VOCAB + vbase) is (k + vbase) & 3. We cp.async 16B from the aligned-down
// address into a 392-float padded row and add the shift when reading frags.
__device__ __forceinline__ void load_bstage(uint32_t bsm, int buf, int s,
                                            const float* __restrict__ W1,
                                            int vbase, int t)
{
    const uint32_t sb = bsm + (uint32_t)buf * BSTAGE;
    const long maxe = (long)D * VOCAB - 4;
    for (int i = t; i < SK * CPR; i += GT) {
        int r = i / CPR, c = i - r * CPR;
        long e0 = (((long)(s * SK + r) * VOCAB + vbase) & ~3L) + (long)c * 4;
        if (e0 > maxe) e0 = maxe;
        cp16(sb + (uint32_t)(r * ROWP + c * 4) * 4, W1 + e0);
    }
}

__global__ __launch_bounds__(GT, 1) void gemm2_kernel(
    const float* __restrict__ W1, const float* __restrict__ b1,
    const void* __restrict__ labels, float* __restrict__ out)
{
    extern __shared__ __align__(1024) char dyn[];
    __shared__ float red[GT];
    __shared__ int   is_last;
    __shared__ float s_lse[B];

    const int t    = threadIdx.x;
    const int wid  = t >> 5, lane = t & 31;
    const int g    = lane >> 2;          // groupID
    const int tig  = lane & 3;           // thread-in-group
    const int vbase = blockIdx.x * VBLK;
    const uint32_t hsm = smem_u32(dyn);
    const uint32_t bsm = hsm + HBYTES;

    // prologue group 0: h (pre-tf32) + B stage 0
    for (int i = t; i < B * (D / 4); i += GT) {         // 8192 16B chunks
        int bb = i >> 8, c = i & 255;
        cp16(hsm + (uint32_t)(bb * HPITCH + c * 4) * 4, g_h + bb * D + c * 4);
    }
    load_bstage(bsm, 0, 0, W1, vbase, t);
    asm volatile("cp.async.commit_group;" ::: "memory");
    load_bstage(bsm, 1, 1, W1, vbase, t);
    asm volatile("cp.async.commit_group;" ::: "memory");
    load_bstage(bsm, 2, 2, W1, vbase, t);
    asm volatile("cp.async.commit_group;" ::: "memory");

    float acc[2][6][4];
    #pragma unroll
    for (int mt = 0; mt < 2; ++mt)
        #pragma unroll
        for (int nt = 0; nt < 6; ++nt)
            #pragma unroll
            for (int r = 0; r < 4; ++r) acc[mt][nt][r] = 0.f;

    const int n0w = wid * 48;

    for (int s = 0; s < NSTG; ++s) {
        asm volatile("cp.async.wait_group 2;" ::: "memory");
        __syncthreads();
        const int buf = s % DEPTH;
        const uint32_t sb = bsm + (uint32_t)buf * BSTAGE;

        #pragma unroll
        for (int kb = 0; kb < SK; kb += 8) {
            const int kabs = s * SK + kb;
            // A fragments: h[b][k], pitch 1028 (bank-conflict-free)
            uint32_t a[2][4];
            #pragma unroll
            for (int mt = 0; mt < 2; ++mt) {
                const int m0 = mt * 16;
                a[mt][0] = __float_as_uint(lds_f(hsm + ((m0 + g)     * HPITCH + kabs + tig)     * 4));
                a[mt][1] = __float_as_uint(lds_f(hsm + ((m0 + g + 8) * HPITCH + kabs + tig)     * 4));
                a[mt][2] = __float_as_uint(lds_f(hsm + ((m0 + g)     * HPITCH + kabs + tig + 4) * 4));
                a[mt][3] = __float_as_uint(lds_f(hsm + ((m0 + g + 8) * HPITCH + kabs + tig + 4) * 4));
            }
            // B fragments: shift same for k and k+4 (差 ≡ 0 mod 4)
            const int sh = (kabs + tig + vbase) & 3;
            const uint32_t r0 = sb + (uint32_t)((kb + tig)     * ROWP + sh) * 4;
            const uint32_t r1 = sb + (uint32_t)((kb + tig + 4) * ROWP + sh) * 4;
            #pragma unroll
            for (int nt = 0; nt < 6; ++nt) {
                const uint32_t co = (uint32_t)(n0w + nt * 8 + g) * 4;
                uint32_t b0 = cvt_tf32(lds_f(r0 + co));
                uint32_t b1 = cvt_tf32(lds_f(r1 + co));
                mma_tf32(acc[0][nt], a[0], b0, b1);
                mma_tf32(acc[1][nt], a[1], b0, b1);
            }
        }
        __syncthreads();
        if (s + DEPTH < NSTG)
            load_bstage(bsm, buf, s + DEPTH, W1, vbase, t);
        asm volatile("cp.async.commit_group;" ::: "memory");
    }
    asm volatile("cp.async.wait_group 0;" ::: "memory");
    __syncthreads();

    // ---- epilogue: fragments -> smem logits (+bias, tail mask) ----
    float* Ls = (float*)dyn;                      // [32][LSS]
    #pragma unroll
    for (int nt = 0; nt < 6; ++nt) {
        const int vloc = n0w + nt * 8 + 2 * tig;
        const int v0 = vbase + vloc, v1 = v0 + 1;
        const float bi0 = b1[v0 < VOCAB ? v0 : (VOCAB - 1)];
        const float bi1 = b1[v1 < VOCAB ? v1 : (VOCAB - 1)];
        #pragma unroll
        for (int mt = 0; mt < 2; ++mt) {
            const int m0 = mt * 16 + g;
            Ls[m0 * LSS + vloc]           = (v0 < VOCAB) ? acc[mt][nt][0] + bi0 : -1e30f;
            Ls[m0 * LSS + vloc + 1]       = (v1 < VOCAB) ? acc[mt][nt][1] + bi1 : -1e30f;
            Ls[(m0 + 8) * LSS + vloc]     = (v0 < VOCAB) ? acc[mt][nt][2] + bi0 : -1e30f;
            Ls[(m0 + 8) * LSS + vloc + 1] = (v1 < VOCAB) ? acc[mt][nt][3] + bi1 : -1e30f;
        }
    }
    __syncthreads();

    // ---- label gather ----
    const int lab64 = g_lab64;
    const long long* lab_ll = (const long long*)labels;
    const int*       lab_i  = (const int*)labels;
    float gg = 0.f;
    for (int i = t; i < B * SEQ; i += GT) {
        int bb = i >> 7;
        int lab = lab64 ? (int)lab_ll[i] : lab_i[i];
        int rel = lab - vbase;
        if (rel >= 0 && rel < VBLK) gg += Ls[bb * LSS + rel];
    }
    red[t] = gg;
    __syncthreads();
    for (int off = GT / 2; off; off >>= 1) {
        if (t < off) red[t] += red[t + off];
        __syncthreads();
    }
    if (t == 0) g_pg[blockIdx.x] = red[0];

    // ---- per-b partial (max, sumexp) over this block's 384 cols ----
    #pragma unroll
    for (int bi = 0; bi < 4; ++bi) {
        const int bb = wid * 4 + bi;
        float m = -1e30f;
        for (int vv = lane; vv < VBLK; vv += 32)
            m = fmaxf(m, Ls[bb * LSS + vv]);
        #pragma unroll
        for (int o = 16; o; o >>= 1)
            m = fmaxf(m, __shfl_xor_sync(0xffffffffu, m, o));
        float sum = 0.f;
        for (int vv = lane; vv < VBLK; vv += 32)
            sum += __expf(Ls[bb * LSS + vv] - m);
        #pragma unroll
        for (int o = 16; o; o >>= 1)
            sum += __shfl_xor_sync(0xffffffffu, sum, o);
        if (lane == 0) {
            g_pmax[blockIdx.x * B + bb] = m;
            g_psum[blockIdx.x * B + bb] = sum;
        }
    }

    // ---- fused finalize: last block reduces all partials ----
    __threadfence();
    __syncthreads();
    if (t == 0) {
        int old = atomicAdd(&g_ctr, 1);
        is_last = (old == NBLK - 1);
    }
    __syncthreads();
    if (!is_last) return;
    __threadfence();

    #pragma unroll
    for (int bi = 0; bi < 4; ++bi) {
        const int bb = wid * 4 + bi;
        float m = -1e30f;
        for (int i = lane; i < NBLK; i += 32)
            m = fmaxf(m, g_pmax[i * B + bb]);
        #pragma unroll
        for (int o = 16; o; o >>= 1)
            m = fmaxf(m, __shfl_xor_sync(0xffffffffu, m, o));
        float sum = 0.f;
        for (int i = lane; i < NBLK; i += 32)
            sum += g_psum[i * B + bb] * __expf(g_pmax[i * B + bb] - m);
        #pragma unroll
        for (int o = 16; o; o >>= 1)
            sum += __shfl_xor_sync(0xffffffffu, sum, o);
        if (lane == 0) s_lse[bb] = m + logf(sum);
    }
    red[t] = (t < NBLK) ? g_pg[t] : 0.f;
    __syncthreads();
    for (int off = GT / 2; off; off >>= 1) {
        if (t < off) red[t] += red[t + off];
        __syncthreads();
    }
    if (t == 0) {
        float L = 0.f;
        #pragma unroll
        for (int bb = 0; bb < B; ++bb) L += s_lse[bb];
        out[0] = L / (float)B - red[0] / (float)(B * SEQ);
        g_ctr = 0;
    }
}

// =========================== launch ======================================
extern "C" void kernel_launch(void* const* d_in, const int* in_sizes, int n_in,
                              void* d_out, int out_size)
{
    const float* z = nullptr; const void* labels = nullptr;
    const float* W0 = nullptr; const float* b0 = nullptr;
    const float* W1 = nullptr; const float* b1 = nullptr;
    for (int i = 0; i < n_in; ++i) {
        switch (in_sizes[i]) {
            case B * D:        z      = (const float*)d_in[i];      break;
            case B * SEQ:      labels = d_in[i];                    break;
            case D * D:        W0     = (const float*)d_in[i];      break;
            case D:            b0     = (const float*)d_in[i];      break;
            case D * VOCAB:    W1     = (const float*)d_in[i];      break;
            case VOCAB:        b1     = (const float*)d_in[i];      break;
            default: break;
        }
    }

    static bool attr_done = false;
    if (!attr_done) {
        cudaFuncSetAttribute(gemm2_kernel,
                             cudaFuncAttributeMaxDynamicSharedMemorySize,
                             SMEM_DYN);
        attr_done = true;
    }

    g1_stage1<<<512, 256>>>(z, W0);
    g1_stage2<<<128, 256>>>(b0, (const long long*)labels);
    gemm2_kernel<<<NBLK, GT, SMEM_DYN>>>(W1, b1, labels, (float*)d_out);
}